// round 15
// baseline (speedup 1.0000x reference)
#include <cuda_runtime.h>
#include <cuda_bf16.h>
#include <stdint.h>
#include <math_constants.h>

#define B_  256
#define C_  345
#define D_  512
#define N_  50000
#define KN  5
#define BM  128                  /* CTA M tile */
#define BN  64                   /* CTA N tile */
#define BK  32                   /* K chunk (bf16 elems) = 64B/row */
#define NCH (D_ / BK)            /* 16 */
#define NT_N 782                 /* ceil(50000 / 64) */
#define NROWS_PAD (NT_N * 64)    /* 50048 */
#define STAGES 4
#define STG_BYTES 15360          /* A 128*80 + B 64*80 */
#define CAND (NT_N * 6)          /* 4692 per row */
#define PREP_BLKS (2 * B_ + 391) /* 903 */

/* ---------------- device scratch (static allocation only) ---------------- */
__device__ __align__(16) float          g_p[B_ * C_];
__device__ float                        g_rowsq[B_];
__device__ __align__(16) float          g_fn[B_ * D_];
__device__ __align__(16) __nv_bfloat16  g_fnb[B_ * D_];
__device__ __align__(16) __nv_bfloat16  g_fbb[(size_t)NROWS_PAD * D_];  /* bf16 bank */
__device__ int                          g_owner[N_];
__device__ __align__(16) float          g_cv[(size_t)B_ * CAND];
__device__ __align__(16) int            g_ci[(size_t)B_ * CAND];
__device__ __align__(16) float          g_tmax[(size_t)B_ * NT_N];   /* per-tile row max */
__device__ float                        g_lossparts[B_];
__device__ float                        g_q2;          /* ||colsum p||^2 */
__device__ unsigned int                 g_tick1 = 0;   /* prep election  */
__device__ unsigned int                 g_tick2 = 0;   /* tail election  */

__device__ __forceinline__ int clampN(int n) {
  return (n < 0) ? 0 : ((n >= N_) ? (N_ - 1) : n);
}
__device__ __forceinline__ bool betterf(float v, int i, float v2, int i2) {
  return (v > v2) || (v == v2 && i < i2);
}
__device__ __forceinline__ void ins6f(float v, int id, float* bv, int* bi) {
  if (betterf(v, id, bv[5], bi[5])) {
    bv[5] = v; bi[5] = id;
#pragma unroll
    for (int j = 5; j > 0; j--) {
      if (betterf(bv[j], bi[j], bv[j - 1], bi[j - 1])) {
        float tv = bv[j]; bv[j] = bv[j - 1]; bv[j - 1] = tv;
        int  ti = bi[j]; bi[j] = bi[j - 1]; bi[j - 1] = ti;
      }
    }
  }
}

/* ---------------- asm helpers ---------------- */
#define LDSM4(r, addr) \
  asm volatile("ldmatrix.sync.aligned.m8n8.x4.shared.b16 {%0,%1,%2,%3}, [%4];" \
    : "=r"((r)[0]), "=r"((r)[1]), "=r"((r)[2]), "=r"((r)[3]) : "r"(addr))
#define CPASYNC16(dst, src) \
  asm volatile("cp.async.cg.shared.global [%0], [%1], 16;" :: "r"(dst), "l"(src))
#define CPCOMMIT() asm volatile("cp.async.commit_group;")
#define CPWAIT2()  asm volatile("cp.async.wait_group 2;")
#define MMA16816(c, a, b0, b1) \
  asm volatile("mma.sync.aligned.m16n8k16.row.col.f32.bf16.bf16.f32 " \
    "{%0,%1,%2,%3}, {%4,%5,%6,%7}, {%8,%9}, {%0,%1,%2,%3};\n" \
    : "+f"((c)[0]), "+f"((c)[1]), "+f"((c)[2]), "+f"((c)[3]) \
    : "r"((a)[0]), "r"((a)[1]), "r"((a)[2]), "r"((a)[3]), "r"(b0), "r"(b1))

/* ------- prep: softmax | fnorm+bf16 | owner-init; elected: scatter + q2 ------- */
__global__ void prep_k(const float* __restrict__ pred, const float* __restrict__ feat,
                       const int* __restrict__ trg) {
  int t = threadIdx.x;
  __shared__ float red[128];
  __shared__ int isLast;
  if (blockIdx.x < B_) {
    int b = blockIdx.x;
    const float* row = pred + (size_t)b * C_;
    float mx = -CUDART_INF_F;
    for (int c = t; c < C_; c += 128) mx = fmaxf(mx, row[c]);
    red[t] = mx; __syncthreads();
    for (int s = 64; s > 0; s >>= 1) { if (t < s) red[t] = fmaxf(red[t], red[t + s]); __syncthreads(); }
    mx = red[0]; __syncthreads();
    float sm = 0.f;
    for (int c = t; c < C_; c += 128) sm += expf(row[c] - mx);
    red[t] = sm; __syncthreads();
    for (int s = 64; s > 0; s >>= 1) { if (t < s) red[t] += red[t + s]; __syncthreads(); }
    float inv = 1.f / red[0]; __syncthreads();
    float sq = 0.f;
    for (int c = t; c < C_; c += 128) {
      float v = expf(row[c] - mx) * inv;
      g_p[(size_t)b * C_ + c] = v;
      sq += v * v;
    }
    red[t] = sq; __syncthreads();
    for (int s = 64; s > 0; s >>= 1) { if (t < s) red[t] += red[t + s]; __syncthreads(); }
    if (t == 0) g_rowsq[b] = red[0];
  } else if (blockIdx.x < 2 * B_) {
    int b = blockIdx.x - B_;
    float4 x = *(const float4*)(feat + (size_t)b * D_ + t * 4);
    float sq = x.x * x.x + x.y * x.y + x.z * x.z + x.w * x.w;
    red[t] = sq; __syncthreads();
    for (int s = 64; s > 0; s >>= 1) { if (t < s) red[t] += red[t + s]; __syncthreads(); }
    float inv = 1.f / fmaxf(sqrtf(red[0]), 1e-12f);
    x.x *= inv; x.y *= inv; x.z *= inv; x.w *= inv;
    *(float4*)(g_fn + (size_t)b * D_ + t * 4) = x;
    __nv_bfloat162 lo = __floats2bfloat162_rn(x.x, x.y);
    __nv_bfloat162 hi = __floats2bfloat162_rn(x.z, x.w);
    uint2 v; v.x = *(uint32_t*)&lo; v.y = *(uint32_t*)&hi;
    *(uint2*)(g_fnb + (size_t)b * D_ + t * 4) = v;
  } else {
    int i = (blockIdx.x - 2 * B_) * 128 + t;
    if (i < N_) g_owner[i] = -1;
  }
  __threadfence();
  __syncthreads();
  if (t == 0) {
    unsigned tk = atomicAdd(&g_tick1, 1u);
    isLast = ((tk % PREP_BLKS) == PREP_BLKS - 1) ? 1 : 0;
  }
  __syncthreads();
  if (isLast) {
    __threadfence();
    for (int j = t; j < B_; j += 128)
      atomicMax(&g_owner[clampN(trg[j])], j);
    /* q2 = || colsum_b p ||^2 : 8 independent accumulators, fixed combine order */
    float q2p = 0.f;
    for (int c = t; c < C_; c += 128) {
      float s0 = 0.f, s1 = 0.f, s2 = 0.f, s3 = 0.f,
            s4 = 0.f, s5 = 0.f, s6 = 0.f, s7 = 0.f;
      for (int bb = 0; bb < B_; bb += 8) {
        s0 += g_p[(size_t)(bb + 0) * C_ + c];
        s1 += g_p[(size_t)(bb + 1) * C_ + c];
        s2 += g_p[(size_t)(bb + 2) * C_ + c];
        s3 += g_p[(size_t)(bb + 3) * C_ + c];
        s4 += g_p[(size_t)(bb + 4) * C_ + c];
        s5 += g_p[(size_t)(bb + 5) * C_ + c];
        s6 += g_p[(size_t)(bb + 6) * C_ + c];
        s7 += g_p[(size_t)(bb + 7) * C_ + c];
      }
      float s = ((s0 + s1) + (s2 + s3)) + ((s4 + s5) + (s6 + s7));
      q2p += s * s;
    }
    __syncthreads();            /* red[] reuse safe */
    red[t] = q2p; __syncthreads();
    for (int s = 64; s > 0; s >>= 1) { if (t < s) red[t] += red[t + s]; __syncthreads(); }
    if (t == 0) g_q2 = red[0];
  }
}

/* ---------------- bank fp32 -> bf16 with inline scatter + pad-zero ---------------- */
__global__ void convert_k(const float* __restrict__ fb) {
  long idx = (long)blockIdx.x * 256 + threadIdx.x;
  long e = idx * 8;
  int row = (int)(e >> 9);
  int col = (int)(e & 511);
  if (row >= N_) {
    *(uint4*)(g_fbb + e) = make_uint4(0, 0, 0, 0);
    return;
  }
  int ow = g_owner[row];
  const float* src = (ow >= 0) ? (g_fn + (size_t)ow * D_) : (fb + (size_t)row * D_);
  float4 f0 = *(const float4*)(src + col);
  float4 f1 = *(const float4*)(src + col + 4);
  __nv_bfloat162 p0 = __floats2bfloat162_rn(f0.x, f0.y);
  __nv_bfloat162 p1 = __floats2bfloat162_rn(f0.z, f0.w);
  __nv_bfloat162 p2 = __floats2bfloat162_rn(f1.x, f1.y);
  __nv_bfloat162 p3 = __floats2bfloat162_rn(f1.z, f1.w);
  uint4 v;
  v.x = *(uint32_t*)&p0; v.y = *(uint32_t*)&p1;
  v.z = *(uint32_t*)&p2; v.w = *(uint32_t*)&p3;
  *(uint4*)(g_fbb + e) = v;
}

/* ---- bf16 GEMM 128x64, warp tile 32x32, 4-stage cp.async, occ-3, fused top-6 ---- */
__global__ void __launch_bounds__(256, 3) gemm_k() {
  __shared__ __align__(16) char smemRaw[STAGES * STG_BYTES];   /* 61440 */

  const int tid  = threadIdx.x;
  const int lane = tid & 31;
  const int warp = tid >> 5;
  const int wm   = warp >> 1;
  const int wn   = warp & 1;
  const int mBase = blockIdx.x * BM;
  const int nBase = blockIdx.y * BN;

  const uint32_t smem0 = (uint32_t)__cvta_generic_to_shared(smemRaw);

  float acc[2][4][4];
#pragma unroll
  for (int i = 0; i < 2; i++)
#pragma unroll
    for (int j = 0; j < 4; j++)
#pragma unroll
      for (int k = 0; k < 4; k++) acc[i][j][k] = 0.f;

  uint32_t aAddr[2], bAddr[2];
  {
    int ar = wm * 32 + (lane & 15);
    int ac = (lane >> 4) * 16;
#pragma unroll
    for (int mi = 0; mi < 2; mi++) aAddr[mi] = smem0 + (ar + mi * 16) * 80 + ac;
    int bn = wn * 32 + (lane & 7) + ((lane >> 4) << 3);
    int bc = ((lane >> 3) & 1) * 16;
#pragma unroll
    for (int n2 = 0; n2 < 2; n2++) bAddr[n2] = smem0 + 10240 + (bn + n2 * 16) * 80 + bc;
  }

  const __nv_bfloat16* gA = g_fnb + (size_t)mBase * D_;
  const __nv_bfloat16* gB = g_fbb + (size_t)nBase * D_;

#define ISSUE_CHUNK(ch, stg) do {                                                   \
    uint32_t so = smem0 + (stg) * STG_BYTES;                                        \
    _Pragma("unroll")                                                               \
    for (int it = 0; it < 3; it++) {                                                \
      int idx = tid + it * 256;                                                     \
      if (idx < 512) {                                                              \
        int r = idx >> 2, c = idx & 3;                                              \
        CPASYNC16(so + r * 80 + c * 16, gA + (size_t)r * D_ + (ch) * BK + c * 8);   \
      } else {                                                                      \
        int j = idx - 512, r = j >> 2, c = j & 3;                                   \
        CPASYNC16(so + 10240 + r * 80 + c * 16,                                     \
                  gB + (size_t)r * D_ + (ch) * BK + c * 8);                         \
      }                                                                             \
    }                                                                               \
  } while (0)

  ISSUE_CHUNK(0, 0); CPCOMMIT();
  ISSUE_CHUNK(1, 1); CPCOMMIT();
  ISSUE_CHUNK(2, 2); CPCOMMIT();

#pragma unroll 1
  for (int ch = 0; ch < NCH; ch++) {
    const int stg = ch & (STAGES - 1);
    CPWAIT2();
    __syncthreads();
    if (ch + 3 < NCH) { ISSUE_CHUNK(ch + 3, (ch + 3) & (STAGES - 1)); CPCOMMIT(); }
    const uint32_t so = stg * STG_BYTES;
#pragma unroll
    for (int ks = 0; ks < 2; ks++) {
      uint32_t a[2][4], b2[2][4];
      const uint32_t koff = so + ks * 32;
#pragma unroll
      for (int mi = 0; mi < 2; mi++) LDSM4(a[mi], aAddr[mi] + koff);
#pragma unroll
      for (int n2 = 0; n2 < 2; n2++) LDSM4(b2[n2], bAddr[n2] + koff);
#pragma unroll
      for (int mi = 0; mi < 2; mi++)
#pragma unroll
        for (int ni = 0; ni < 4; ni++)
          MMA16816(acc[mi][ni], a[mi], b2[ni >> 1][(ni & 1) * 2], b2[ni >> 1][(ni & 1) * 2 + 1]);
    }
  }
  __syncthreads();

  /* ---- fused epilogue: per-row top-6 of this 64-col tile + tile max ---- */
  float* scanTile = (float*)smemRaw;            /* 128*65*4 = 33280 */
  float* mbV = (float*)(smemRaw + 33280);       /* [128][2][6] */
  int*   mbI = (int*)(smemRaw + 39424);         /* [128][2][6] */

#pragma unroll
  for (int mi = 0; mi < 2; mi++) {
    int r = wm * 32 + mi * 16 + (lane >> 2);
#pragma unroll
    for (int ni = 0; ni < 4; ni++) {
      int c = wn * 32 + ni * 8 + (lane & 3) * 2;
      scanTile[r * 65 + c]           = acc[mi][ni][0];
      scanTile[r * 65 + c + 1]       = acc[mi][ni][1];
      scanTile[(r + 8) * 65 + c]     = acc[mi][ni][2];
      scanTile[(r + 8) * 65 + c + 1] = acc[mi][ni][3];
    }
  }
  __syncthreads();
  {
    int row = tid & 127;
    int seg = tid >> 7;
    int cs  = seg * 32;
    float bv[6]; int bi[6];
#pragma unroll
    for (int j = 0; j < 6; j++) { bv[j] = -CUDART_INF_F; bi[j] = 0x7fffffff; }
    if (nBase + BN <= N_) {
#pragma unroll 4
      for (int i = 0; i < 32; i++)
        ins6f(scanTile[row * 65 + cs + i], nBase + cs + i, bv, bi);
    } else {
#pragma unroll 4
      for (int i = 0; i < 32; i++) {
        int gcol = nBase + cs + i;
        if (gcol < N_) ins6f(scanTile[row * 65 + cs + i], gcol, bv, bi);
      }
    }
#pragma unroll
    for (int j = 0; j < 6; j++) {
      mbV[(row * 2 + seg) * 6 + j] = bv[j];
      mbI[(row * 2 + seg) * 6 + j] = bi[j];
    }
  }
  __syncthreads();
  if (tid < 128) {
    int row = tid;
    float bv[6]; int bi[6];
#pragma unroll
    for (int j = 0; j < 6; j++) { bv[j] = -CUDART_INF_F; bi[j] = 0x7fffffff; }
#pragma unroll
    for (int s = 0; s < 2; s++)
#pragma unroll
      for (int j = 0; j < 6; j++)
        ins6f(mbV[(row * 2 + s) * 6 + j], mbI[(row * 2 + s) * 6 + j], bv, bi);
    int grow = mBase + row;
    size_t base = ((size_t)grow * NT_N + blockIdx.y) * 6;
#pragma unroll
    for (int j = 0; j < 6; j++) { g_cv[base + j] = bv[j]; g_ci[base + j] = bi[j]; }
    g_tmax[(size_t)grow * NT_N + blockIdx.y] = bv[0];   /* dense tile-max */
  }
}

/* ---- tail: top-6 tiles by tile-max (exact pruning) -> gather 36 cands ->
        top-6 -> warp-parallel KL; elected block: tiny final -> out[0] ---- */
__global__ void tail_k(const float* __restrict__ sb, float* __restrict__ out) {
  const int b = blockIdx.x, t = threadIdx.x;     /* 256 threads */
  const int lane = t & 31, warp = t >> 5;
  __shared__ float sv[256 * 6];
  __shared__ int   si[256 * 6];
  __shared__ float sv2[96];  __shared__ int si2[96];
  __shared__ int   stile[6];
  __shared__ float cV[36];   __shared__ int cI[36];
  __shared__ int   sidx[KN];
  __shared__ float redw[8];
  __shared__ int   isLast;

  /* phase 1: top-6 tiles by per-tile max (782 floats, ~3 per thread) */
  {
    const float* tm = g_tmax + (size_t)b * NT_N;
    float bv[6]; int bi[6];
#pragma unroll
    for (int j = 0; j < 6; j++) { bv[j] = -CUDART_INF_F; bi[j] = 0x7fffffff; }
    for (int e = t; e < NT_N; e += 256)
      ins6f(tm[e], e, bv, bi);
#pragma unroll
    for (int j = 0; j < 6; j++) { sv[t * 6 + j] = bv[j]; si[t * 6 + j] = bi[j]; }
  }
  __syncthreads();
  if (t < 16) {
    float mv[6]; int mi_[6];
#pragma unroll
    for (int j = 0; j < 6; j++) { mv[j] = -CUDART_INF_F; mi_[j] = 0x7fffffff; }
    for (int src = t * 16; src < t * 16 + 16; src++)
      for (int j = 0; j < 6; j++)
        ins6f(sv[src * 6 + j], si[src * 6 + j], mv, mi_);
#pragma unroll
    for (int j = 0; j < 6; j++) { sv2[t * 6 + j] = mv[j]; si2[t * 6 + j] = mi_[j]; }
  }
  __syncthreads();
  if (t == 0) {
    float mv[6]; int mi_[6];
#pragma unroll
    for (int j = 0; j < 6; j++) { mv[j] = -CUDART_INF_F; mi_[j] = 0x7fffffff; }
    for (int e = 0; e < 96; e++) ins6f(sv2[e], si2[e], mv, mi_);
#pragma unroll
    for (int j = 0; j < 6; j++) stile[j] = mi_[j];
  }
  __syncthreads();

  /* phase 2: gather the 6 chosen tiles' candidate lists (36 entries) */
  if (t < 36) {
    int tile = stile[t / 6];
    size_t base = ((size_t)b * NT_N + tile) * 6 + (t % 6);
    cV[t] = g_cv[base];
    cI[t] = g_ci[base];
  }
  __syncthreads();
  if (t == 0) {
    float mv[6]; int mi_[6];
#pragma unroll
    for (int j = 0; j < 6; j++) { mv[j] = -CUDART_INF_F; mi_[j] = 0x7fffffff; }
    for (int e = 0; e < 36; e++) ins6f(cV[e], cI[e], mv, mi_);
#pragma unroll
    for (int j = 1; j < 6; j++) sidx[j - 1] = mi_[j];   /* drop rank-0 */
  }
  __syncthreads();

  /* warp-parallel KL: warp k (k<5) owns neighbor k; 5 chains run concurrently */
  if (warp < KN) {
    int n  = sidx[warp];
    int ow = g_owner[n];
    const float* srow = (ow >= 0) ? (g_p + (size_t)ow * C_)
                                  : (sb + (size_t)n * C_);
    float ws = 0.f;
    for (int c = lane; c < C_; c += 32) {
      float s = srow[c];
      ws += s * (logf(s) - g_p[(size_t)b * C_ + c]);
    }
#pragma unroll
    for (int o = 16; o > 0; o >>= 1) ws += __shfl_xor_sync(0xffffffffu, ws, o);
    if (lane == 0) redw[warp] = ws;
  }
  __syncthreads();
  if (t == 0)
    g_lossparts[b] = ((redw[0] + redw[1]) + (redw[2] + redw[3])) + redw[4];

  /* election: last block does the (now tiny) final reduction */
  __threadfence();
  __syncthreads();
  if (t == 0) {
    unsigned tk = atomicAdd(&g_tick2, 1u);
    isLast = ((tk % B_) == B_ - 1) ? 1 : 0;
  }
  __syncthreads();
  if (isLast) {
    __threadfence();
    __shared__ float r1[256], r3[256];
    r1[t] = g_lossparts[t];
    r3[t] = g_rowsq[t];
    __syncthreads();
    for (int s = 128; s > 0; s >>= 1) {
      if (t < s) { r1[t] += r1[t + s]; r3[t] += r3[t + s]; }
      __syncthreads();
    }
    if (t == 0) out[0] = r1[0] / (float)B_ + 1.0f * ((g_q2 - r3[0]) / (float)B_);
  }
}

/* ---------------- launch: 4 kernels total ---------------- */
extern "C" void kernel_launch(void* const* d_in, const int* in_sizes, int n_in,
                              void* d_out, int out_size) {
  (void)in_sizes; (void)n_in; (void)out_size;
  const float* feat = (const float*)d_in[0];
  const float* pred = (const float*)d_in[1];
  const float* fb   = (const float*)d_in[2];
  const float* sb   = (const float*)d_in[3];
  const int*   trg  = (const int*)d_in[4];

  prep_k<<<PREP_BLKS, 128>>>(pred, feat, trg);
  convert_k<<<12512, 256>>>(fb);
  dim3 g(2, NT_N);
  gemm_k<<<g, 256>>>();
  tail_k<<<B_, 256>>>(sb, (float*)d_out);
}

// round 16
// speedup vs baseline: 1.0537x; 1.0537x over previous
#include <cuda_runtime.h>
#include <cuda_bf16.h>
#include <stdint.h>
#include <math_constants.h>

#define B_  256
#define C_  345
#define D_  512
#define N_  50000
#define KN  5
#define BM  128                  /* CTA M tile */
#define BN  64                   /* CTA N tile */
#define BK  32                   /* K chunk (bf16 elems) = 64B/row */
#define NCH (D_ / BK)            /* 16 */
#define NT_N 782                 /* ceil(50000 / 64) */
#define NROWS_PAD (NT_N * 64)    /* 50048 */
#define STAGES 4
#define STG_BYTES 15360          /* A 128*80 + B 64*80 */
#define CAND (NT_N * 6)          /* 4692 per row */
#define PREP_BLKS (2 * B_ + 391) /* 903 */

/* ---------------- device scratch (static allocation only) ---------------- */
__device__ __align__(16) float          g_p[B_ * C_];
__device__ float                        g_rowsq[B_];
__device__ __align__(16) float          g_fn[B_ * D_];
__device__ __align__(16) __nv_bfloat16  g_fnb[B_ * D_];
__device__ __align__(16) __nv_bfloat16  g_fbb[(size_t)NROWS_PAD * D_];  /* bf16 bank */
__device__ int                          g_owner[N_];
__device__ __align__(16) float          g_cv[(size_t)B_ * CAND];
__device__ __align__(16) int            g_ci[(size_t)B_ * CAND];
__device__ __align__(16) float          g_tmax[(size_t)B_ * NT_N];   /* per-tile row max */
__device__ float                        g_lossparts[B_];
__device__ float                        g_q[C_];       /* colsum of p (by tail block 0) */
__device__ unsigned int                 g_tick1 = 0;   /* prep election  */
__device__ unsigned int                 g_tick2 = 0;   /* tail election  */

__device__ __forceinline__ int clampN(int n) {
  return (n < 0) ? 0 : ((n >= N_) ? (N_ - 1) : n);
}
__device__ __forceinline__ bool betterf(float v, int i, float v2, int i2) {
  return (v > v2) || (v == v2 && i < i2);
}
__device__ __forceinline__ void ins6f(float v, int id, float* bv, int* bi) {
  if (betterf(v, id, bv[5], bi[5])) {
    bv[5] = v; bi[5] = id;
#pragma unroll
    for (int j = 5; j > 0; j--) {
      if (betterf(bv[j], bi[j], bv[j - 1], bi[j - 1])) {
        float tv = bv[j]; bv[j] = bv[j - 1]; bv[j - 1] = tv;
        int  ti = bi[j]; bi[j] = bi[j - 1]; bi[j - 1] = ti;
      }
    }
  }
}

/* ---------------- asm helpers ---------------- */
#define LDSM4(r, addr) \
  asm volatile("ldmatrix.sync.aligned.m8n8.x4.shared.b16 {%0,%1,%2,%3}, [%4];" \
    : "=r"((r)[0]), "=r"((r)[1]), "=r"((r)[2]), "=r"((r)[3]) : "r"(addr))
#define CPASYNC16(dst, src) \
  asm volatile("cp.async.cg.shared.global [%0], [%1], 16;" :: "r"(dst), "l"(src))
#define CPCOMMIT() asm volatile("cp.async.commit_group;")
#define CPWAIT2()  asm volatile("cp.async.wait_group 2;")
#define MMA16816(c, a, b0, b1) \
  asm volatile("mma.sync.aligned.m16n8k16.row.col.f32.bf16.bf16.f32 " \
    "{%0,%1,%2,%3}, {%4,%5,%6,%7}, {%8,%9}, {%0,%1,%2,%3};\n" \
    : "+f"((c)[0]), "+f"((c)[1]), "+f"((c)[2]), "+f"((c)[3]) \
    : "r"((a)[0]), "r"((a)[1]), "r"((a)[2]), "r"((a)[3]), "r"(b0), "r"(b1))

/* ------- prep: softmax | fnorm+bf16 | owner-init; elected: trg scatter ------- */
__global__ void prep_k(const float* __restrict__ pred, const float* __restrict__ feat,
                       const int* __restrict__ trg) {
  int t = threadIdx.x;
  __shared__ float red[128];
  __shared__ int isLast;
  if (blockIdx.x < B_) {
    int b = blockIdx.x;
    const float* row = pred + (size_t)b * C_;
    float mx = -CUDART_INF_F;
    for (int c = t; c < C_; c += 128) mx = fmaxf(mx, row[c]);
    red[t] = mx; __syncthreads();
    for (int s = 64; s > 0; s >>= 1) { if (t < s) red[t] = fmaxf(red[t], red[t + s]); __syncthreads(); }
    mx = red[0]; __syncthreads();
    float sm = 0.f;
    for (int c = t; c < C_; c += 128) sm += expf(row[c] - mx);
    red[t] = sm; __syncthreads();
    for (int s = 64; s > 0; s >>= 1) { if (t < s) red[t] += red[t + s]; __syncthreads(); }
    float inv = 1.f / red[0]; __syncthreads();
    float sq = 0.f;
    for (int c = t; c < C_; c += 128) {
      float v = expf(row[c] - mx) * inv;
      g_p[(size_t)b * C_ + c] = v;
      sq += v * v;
    }
    red[t] = sq; __syncthreads();
    for (int s = 64; s > 0; s >>= 1) { if (t < s) red[t] += red[t + s]; __syncthreads(); }
    if (t == 0) g_rowsq[b] = red[0];
  } else if (blockIdx.x < 2 * B_) {
    int b = blockIdx.x - B_;
    float4 x = *(const float4*)(feat + (size_t)b * D_ + t * 4);
    float sq = x.x * x.x + x.y * x.y + x.z * x.z + x.w * x.w;
    red[t] = sq; __syncthreads();
    for (int s = 64; s > 0; s >>= 1) { if (t < s) red[t] += red[t + s]; __syncthreads(); }
    float inv = 1.f / fmaxf(sqrtf(red[0]), 1e-12f);
    x.x *= inv; x.y *= inv; x.z *= inv; x.w *= inv;
    *(float4*)(g_fn + (size_t)b * D_ + t * 4) = x;
    __nv_bfloat162 lo = __floats2bfloat162_rn(x.x, x.y);
    __nv_bfloat162 hi = __floats2bfloat162_rn(x.z, x.w);
    uint2 v; v.x = *(uint32_t*)&lo; v.y = *(uint32_t*)&hi;
    *(uint2*)(g_fnb + (size_t)b * D_ + t * 4) = v;
  } else {
    int i = (blockIdx.x - 2 * B_) * 128 + t;
    if (i < N_) g_owner[i] = -1;
  }
  __threadfence();
  __syncthreads();
  if (t == 0) {
    unsigned tk = atomicAdd(&g_tick1, 1u);
    isLast = ((tk % PREP_BLKS) == PREP_BLKS - 1) ? 1 : 0;
  }
  __syncthreads();
  if (isLast) {
    __threadfence();
    for (int j = t; j < B_; j += 128)
      atomicMax(&g_owner[clampN(trg[j])], j);
  }
}

/* ---------------- bank fp32 -> bf16 with inline scatter + pad-zero ---------------- */
__global__ void convert_k(const float* __restrict__ fb) {
  long idx = (long)blockIdx.x * 256 + threadIdx.x;
  long e = idx * 8;
  int row = (int)(e >> 9);
  int col = (int)(e & 511);
  if (row >= N_) {
    *(uint4*)(g_fbb + e) = make_uint4(0, 0, 0, 0);
    return;
  }
  int ow = g_owner[row];
  const float* src = (ow >= 0) ? (g_fn + (size_t)ow * D_) : (fb + (size_t)row * D_);
  float4 f0 = *(const float4*)(src + col);
  float4 f1 = *(const float4*)(src + col + 4);
  __nv_bfloat162 p0 = __floats2bfloat162_rn(f0.x, f0.y);
  __nv_bfloat162 p1 = __floats2bfloat162_rn(f0.z, f0.w);
  __nv_bfloat162 p2 = __floats2bfloat162_rn(f1.x, f1.y);
  __nv_bfloat162 p3 = __floats2bfloat162_rn(f1.z, f1.w);
  uint4 v;
  v.x = *(uint32_t*)&p0; v.y = *(uint32_t*)&p1;
  v.z = *(uint32_t*)&p2; v.w = *(uint32_t*)&p3;
  *(uint4*)(g_fbb + e) = v;
}

/* ---- bf16 GEMM 128x64, warp tile 32x32, 4-stage cp.async, occ-3, fused top-6 ---- */
__global__ void __launch_bounds__(256, 3) gemm_k() {
  __shared__ __align__(16) char smemRaw[STAGES * STG_BYTES];   /* 61440 */

  const int tid  = threadIdx.x;
  const int lane = tid & 31;
  const int warp = tid >> 5;
  const int wm   = warp >> 1;
  const int wn   = warp & 1;
  const int mBase = blockIdx.x * BM;
  const int nBase = blockIdx.y * BN;

  const uint32_t smem0 = (uint32_t)__cvta_generic_to_shared(smemRaw);

  float acc[2][4][4];
#pragma unroll
  for (int i = 0; i < 2; i++)
#pragma unroll
    for (int j = 0; j < 4; j++)
#pragma unroll
      for (int k = 0; k < 4; k++) acc[i][j][k] = 0.f;

  uint32_t aAddr[2], bAddr[2];
  {
    int ar = wm * 32 + (lane & 15);
    int ac = (lane >> 4) * 16;
#pragma unroll
    for (int mi = 0; mi < 2; mi++) aAddr[mi] = smem0 + (ar + mi * 16) * 80 + ac;
    int bn = wn * 32 + (lane & 7) + ((lane >> 4) << 3);
    int bc = ((lane >> 3) & 1) * 16;
#pragma unroll
    for (int n2 = 0; n2 < 2; n2++) bAddr[n2] = smem0 + 10240 + (bn + n2 * 16) * 80 + bc;
  }

  const __nv_bfloat16* gA = g_fnb + (size_t)mBase * D_;
  const __nv_bfloat16* gB = g_fbb + (size_t)nBase * D_;

#define ISSUE_CHUNK(ch, stg) do {                                                   \
    uint32_t so = smem0 + (stg) * STG_BYTES;                                        \
    _Pragma("unroll")                                                               \
    for (int it = 0; it < 3; it++) {                                                \
      int idx = tid + it * 256;                                                     \
      if (idx < 512) {                                                              \
        int r = idx >> 2, c = idx & 3;                                              \
        CPASYNC16(so + r * 80 + c * 16, gA + (size_t)r * D_ + (ch) * BK + c * 8);   \
      } else {                                                                      \
        int j = idx - 512, r = j >> 2, c = j & 3;                                   \
        CPASYNC16(so + 10240 + r * 80 + c * 16,                                     \
                  gB + (size_t)r * D_ + (ch) * BK + c * 8);                         \
      }                                                                             \
    }                                                                               \
  } while (0)

  ISSUE_CHUNK(0, 0); CPCOMMIT();
  ISSUE_CHUNK(1, 1); CPCOMMIT();
  ISSUE_CHUNK(2, 2); CPCOMMIT();

#pragma unroll 1
  for (int ch = 0; ch < NCH; ch++) {
    const int stg = ch & (STAGES - 1);
    CPWAIT2();
    __syncthreads();
    if (ch + 3 < NCH) { ISSUE_CHUNK(ch + 3, (ch + 3) & (STAGES - 1)); CPCOMMIT(); }
    const uint32_t so = stg * STG_BYTES;
#pragma unroll
    for (int ks = 0; ks < 2; ks++) {
      uint32_t a[2][4], b2[2][4];
      const uint32_t koff = so + ks * 32;
#pragma unroll
      for (int mi = 0; mi < 2; mi++) LDSM4(a[mi], aAddr[mi] + koff);
#pragma unroll
      for (int n2 = 0; n2 < 2; n2++) LDSM4(b2[n2], bAddr[n2] + koff);
#pragma unroll
      for (int mi = 0; mi < 2; mi++)
#pragma unroll
        for (int ni = 0; ni < 4; ni++)
          MMA16816(acc[mi][ni], a[mi], b2[ni >> 1][(ni & 1) * 2], b2[ni >> 1][(ni & 1) * 2 + 1]);
    }
  }
  __syncthreads();

  /* ---- fused epilogue: per-row top-6 of this 64-col tile + tile max ---- */
  float* scanTile = (float*)smemRaw;            /* 128*65*4 = 33280 */
  float* mbV = (float*)(smemRaw + 33280);       /* [128][2][6] */
  int*   mbI = (int*)(smemRaw + 39424);         /* [128][2][6] */

#pragma unroll
  for (int mi = 0; mi < 2; mi++) {
    int r = wm * 32 + mi * 16 + (lane >> 2);
#pragma unroll
    for (int ni = 0; ni < 4; ni++) {
      int c = wn * 32 + ni * 8 + (lane & 3) * 2;
      scanTile[r * 65 + c]           = acc[mi][ni][0];
      scanTile[r * 65 + c + 1]       = acc[mi][ni][1];
      scanTile[(r + 8) * 65 + c]     = acc[mi][ni][2];
      scanTile[(r + 8) * 65 + c + 1] = acc[mi][ni][3];
    }
  }
  __syncthreads();
  {
    int row = tid & 127;
    int seg = tid >> 7;
    int cs  = seg * 32;
    float bv[6]; int bi[6];
#pragma unroll
    for (int j = 0; j < 6; j++) { bv[j] = -CUDART_INF_F; bi[j] = 0x7fffffff; }
    if (nBase + BN <= N_) {
#pragma unroll 4
      for (int i = 0; i < 32; i++)
        ins6f(scanTile[row * 65 + cs + i], nBase + cs + i, bv, bi);
    } else {
#pragma unroll 4
      for (int i = 0; i < 32; i++) {
        int gcol = nBase + cs + i;
        if (gcol < N_) ins6f(scanTile[row * 65 + cs + i], gcol, bv, bi);
      }
    }
#pragma unroll
    for (int j = 0; j < 6; j++) {
      mbV[(row * 2 + seg) * 6 + j] = bv[j];
      mbI[(row * 2 + seg) * 6 + j] = bi[j];
    }
  }
  __syncthreads();
  if (tid < 128) {
    int row = tid;
    float bv[6]; int bi[6];
#pragma unroll
    for (int j = 0; j < 6; j++) { bv[j] = -CUDART_INF_F; bi[j] = 0x7fffffff; }
#pragma unroll
    for (int s = 0; s < 2; s++)
#pragma unroll
      for (int j = 0; j < 6; j++)
        ins6f(mbV[(row * 2 + s) * 6 + j], mbI[(row * 2 + s) * 6 + j], bv, bi);
    int grow = mBase + row;
    size_t base = ((size_t)grow * NT_N + blockIdx.y) * 6;
#pragma unroll
    for (int j = 0; j < 6; j++) { g_cv[base + j] = bv[j]; g_ci[base + j] = bi[j]; }
    g_tmax[(size_t)grow * NT_N + blockIdx.y] = bv[0];   /* dense tile-max */
  }
}

/* ---- tail: top-6 tiles by tile-max (exact) -> gather 36 cands -> top-6 ->
        warp-parallel KL; block 0 also computes colsum q (parallel, deterministic);
        elected block: tiny final -> out[0] ---- */
__global__ void tail_k(const float* __restrict__ sb, float* __restrict__ out) {
  const int b = blockIdx.x, t = threadIdx.x;     /* 256 threads */
  const int lane = t & 31, warp = t >> 5;
  __shared__ float sv[256 * 6];
  __shared__ int   si[256 * 6];
  __shared__ float sv2[96];  __shared__ int si2[96];
  __shared__ int   stile[6];
  __shared__ float cV[36];   __shared__ int cI[36];
  __shared__ int   sidx[KN];
  __shared__ float redw[8];
  __shared__ int   isLast;

  /* phase 1: top-6 tiles by per-tile max (782 floats, ~3 per thread) */
  {
    const float* tm = g_tmax + (size_t)b * NT_N;
    float bv[6]; int bi[6];
#pragma unroll
    for (int j = 0; j < 6; j++) { bv[j] = -CUDART_INF_F; bi[j] = 0x7fffffff; }
    for (int e = t; e < NT_N; e += 256)
      ins6f(tm[e], e, bv, bi);
#pragma unroll
    for (int j = 0; j < 6; j++) { sv[t * 6 + j] = bv[j]; si[t * 6 + j] = bi[j]; }
  }
  __syncthreads();
  if (t < 16) {
    float mv[6]; int mi_[6];
#pragma unroll
    for (int j = 0; j < 6; j++) { mv[j] = -CUDART_INF_F; mi_[j] = 0x7fffffff; }
    for (int src = t * 16; src < t * 16 + 16; src++)
      for (int j = 0; j < 6; j++)
        ins6f(sv[src * 6 + j], si[src * 6 + j], mv, mi_);
#pragma unroll
    for (int j = 0; j < 6; j++) { sv2[t * 6 + j] = mv[j]; si2[t * 6 + j] = mi_[j]; }
  }
  __syncthreads();
  if (t == 0) {
    float mv[6]; int mi_[6];
#pragma unroll
    for (int j = 0; j < 6; j++) { mv[j] = -CUDART_INF_F; mi_[j] = 0x7fffffff; }
    for (int e = 0; e < 96; e++) ins6f(sv2[e], si2[e], mv, mi_);
#pragma unroll
    for (int j = 0; j < 6; j++) stile[j] = mi_[j];
  }
  __syncthreads();

  /* phase 2: gather the 6 chosen tiles' candidate lists (36 entries) */
  if (t < 36) {
    int tile = stile[t / 6];
    size_t base = ((size_t)b * NT_N + tile) * 6 + (t % 6);
    cV[t] = g_cv[base];
    cI[t] = g_ci[base];
  }
  __syncthreads();
  if (t == 0) {
    float mv[6]; int mi_[6];
#pragma unroll
    for (int j = 0; j < 6; j++) { mv[j] = -CUDART_INF_F; mi_[j] = 0x7fffffff; }
    for (int e = 0; e < 36; e++) ins6f(cV[e], cI[e], mv, mi_);
#pragma unroll
    for (int j = 1; j < 6; j++) sidx[j - 1] = mi_[j];   /* drop rank-0 */
  }
  __syncthreads();

  /* warp-parallel KL: warp k (k<5) owns neighbor k */
  if (warp < KN) {
    int n  = sidx[warp];
    int ow = g_owner[n];
    const float* srow = (ow >= 0) ? (g_p + (size_t)ow * C_)
                                  : (sb + (size_t)n * C_);
    float ws = 0.f;
    for (int c = lane; c < C_; c += 32) {
      float s = srow[c];
      ws += s * (logf(s) - g_p[(size_t)b * C_ + c]);
    }
#pragma unroll
    for (int o = 16; o > 0; o >>= 1) ws += __shfl_xor_sync(0xffffffffu, ws, o);
    if (lane == 0) redw[warp] = ws;
  }
  __syncthreads();
  if (t == 0)
    g_lossparts[b] = ((redw[0] + redw[1]) + (redw[2] + redw[3])) + redw[4];

  /* block 0 only: deterministic colsum q[c] = sum_b p[b][c] (coalesced lanes) */
  if (b == 0) {
    for (int c = t; c < C_; c += 256) {
      float s0 = 0.f, s1 = 0.f, s2 = 0.f, s3 = 0.f,
            s4 = 0.f, s5 = 0.f, s6 = 0.f, s7 = 0.f;
      for (int bb = 0; bb < B_; bb += 8) {
        s0 += g_p[(size_t)(bb + 0) * C_ + c];
        s1 += g_p[(size_t)(bb + 1) * C_ + c];
        s2 += g_p[(size_t)(bb + 2) * C_ + c];
        s3 += g_p[(size_t)(bb + 3) * C_ + c];
        s4 += g_p[(size_t)(bb + 4) * C_ + c];
        s5 += g_p[(size_t)(bb + 5) * C_ + c];
        s6 += g_p[(size_t)(bb + 6) * C_ + c];
        s7 += g_p[(size_t)(bb + 7) * C_ + c];
      }
      g_q[c] = ((s0 + s1) + (s2 + s3)) + ((s4 + s5) + (s6 + s7));
    }
  }

  /* election: last block does the (tiny) final reduction */
  __threadfence();
  __syncthreads();
  if (t == 0) {
    unsigned tk = atomicAdd(&g_tick2, 1u);
    isLast = ((tk % B_) == B_ - 1) ? 1 : 0;
  }
  __syncthreads();
  if (isLast) {
    __threadfence();
    __shared__ float r1[256], r2[256], r3[256];
    float q2 = 0.f;
    for (int c = t; c < C_; c += 256) { float q = g_q[c]; q2 += q * q; }
    r1[t] = g_lossparts[t];
    r2[t] = q2;
    r3[t] = g_rowsq[t];
    __syncthreads();
    for (int s = 128; s > 0; s >>= 1) {
      if (t < s) { r1[t] += r1[t + s]; r2[t] += r2[t + s]; r3[t] += r3[t + s]; }
      __syncthreads();
    }
    if (t == 0) out[0] = r1[0] / (float)B_ + 1.0f * ((r2[0] - r3[0]) / (float)B_);
  }
}

/* ---------------- launch: 4 kernels total ---------------- */
extern "C" void kernel_launch(void* const* d_in, const int* in_sizes, int n_in,
                              void* d_out, int out_size) {
  (void)in_sizes; (void)n_in; (void)out_size;
  const float* feat = (const float*)d_in[0];
  const float* pred = (const float*)d_in[1];
  const float* fb   = (const float*)d_in[2];
  const float* sb   = (const float*)d_in[3];
  const int*   trg  = (const int*)d_in[4];

  prep_k<<<PREP_BLKS, 128>>>(pred, feat, trg);
  convert_k<<<12512, 256>>>(fb);
  dim3 g(2, NT_N);
  gemm_k<<<g, 256>>>();
  tail_k<<<B_, 256>>>(sb, (float*)d_out);
}

// round 17
// speedup vs baseline: 1.2513x; 1.1875x over previous
#include <cuda_runtime.h>
#include <cuda_bf16.h>
#include <stdint.h>
#include <math_constants.h>

#define B_  256
#define C_  345
#define D_  512
#define N_  50000
#define KN  5
#define BM  128                  /* CTA M tile */
#define BN  64                   /* CTA N tile */
#define BK  32                   /* K chunk (bf16 elems) = 64B/row */
#define NCH (D_ / BK)            /* 16 */
#define NT_N 782                 /* ceil(50000 / 64) */
#define NROWS_PAD (NT_N * 64)    /* 50048 */
#define STAGES 4
#define STG_BYTES 15360          /* A 128*80 + B 64*80 */
#define CAND (NT_N * 6)          /* 4692 per row */
#define PREP_BLKS (2 * B_ + 391) /* 903 */
#define CONV_BLKS 12512

typedef unsigned long long u64;

/* ---------------- device scratch (static allocation only) ---------------- */
__device__ __align__(16) float          g_p[B_ * C_];
__device__ float                        g_rowsq[B_];
__device__ __align__(16) float          g_fn[B_ * D_];
__device__ __align__(16) __nv_bfloat16  g_fnb[B_ * D_];
__device__ __align__(16) __nv_bfloat16  g_fbb[(size_t)NROWS_PAD * D_];
__device__ int                          g_owner[N_];
__device__ __align__(16) u64            g_cand[(size_t)B_ * CAND];    /* packed keys */
__device__ __align__(16) u64            g_tmaxk[(size_t)B_ * NT_N];   /* tile-max keys */
__device__ float                        g_lossparts[B_];
__device__ float                        g_q[C_];
__device__ unsigned int                 g_tick1 = 0;
__device__ unsigned int                 g_tick2 = 0;

__device__ __forceinline__ int clampN(int n) {
  return (n < 0) ? 0 : ((n >= N_) ? (N_ - 1) : n);
}

/* packed key: (ordered(v) << 32) | (0xFFFFFFFF - idx); u64 '>' == (v desc, idx asc) */
__device__ __forceinline__ u64 packkey(float v, int idx) {
  unsigned u = __float_as_uint(v);
  u = (v >= 0.f) ? (u | 0x80000000u) : ~u;
  return ((u64)u << 32) | (unsigned)(0xFFFFFFFFu - idx);
}
__device__ __forceinline__ int keyidx(u64 k) {
  return (int)(0xFFFFFFFFu - (unsigned)k);
}
/* guarded branchless bubble insert into desc-sorted s[0..5] */
__device__ __forceinline__ void ins6k(u64 x, u64* s) {
  if (x > s[5]) {
    u64 y = x;
#pragma unroll
    for (int j = 0; j < 6; j++) {
      u64 mx = (s[j] > y) ? s[j] : y;
      u64 mn = (s[j] > y) ? y : s[j];
      s[j] = mx; y = mn;
    }
  }
}

/* ---------------- asm helpers ---------------- */
#define LDSM4(r, addr) \
  asm volatile("ldmatrix.sync.aligned.m8n8.x4.shared.b16 {%0,%1,%2,%3}, [%4];" \
    : "=r"((r)[0]), "=r"((r)[1]), "=r"((r)[2]), "=r"((r)[3]) : "r"(addr))
#define CPASYNC16(dst, src) \
  asm volatile("cp.async.cg.shared.global [%0], [%1], 16;" :: "r"(dst), "l"(src))
#define CPCOMMIT() asm volatile("cp.async.commit_group;")
#define CPWAIT2()  asm volatile("cp.async.wait_group 2;")
#define MMA16816(c, a, b0, b1) \
  asm volatile("mma.sync.aligned.m16n8k16.row.col.f32.bf16.bf16.f32 " \
    "{%0,%1,%2,%3}, {%4,%5,%6,%7}, {%8,%9}, {%0,%1,%2,%3};\n" \
    : "+f"((c)[0]), "+f"((c)[1]), "+f"((c)[2]), "+f"((c)[3]) \
    : "r"((a)[0]), "r"((a)[1]), "r"((a)[2]), "r"((a)[3]), "r"(b0), "r"(b1))

/* ------- prep: softmax | fnorm+bf16 | owner-init; elected: trg scatter ------- */
__global__ void prep_k(const float* __restrict__ pred, const float* __restrict__ feat,
                       const int* __restrict__ trg) {
  int t = threadIdx.x;
  __shared__ float red[128];
  __shared__ int isLast;
  if (blockIdx.x < B_) {
    int b = blockIdx.x;
    const float* row = pred + (size_t)b * C_;
    float mx = -CUDART_INF_F;
    for (int c = t; c < C_; c += 128) mx = fmaxf(mx, row[c]);
    red[t] = mx; __syncthreads();
    for (int s = 64; s > 0; s >>= 1) { if (t < s) red[t] = fmaxf(red[t], red[t + s]); __syncthreads(); }
    mx = red[0]; __syncthreads();
    float sm = 0.f;
    for (int c = t; c < C_; c += 128) sm += expf(row[c] - mx);
    red[t] = sm; __syncthreads();
    for (int s = 64; s > 0; s >>= 1) { if (t < s) red[t] += red[t + s]; __syncthreads(); }
    float inv = 1.f / red[0]; __syncthreads();
    float sq = 0.f;
    for (int c = t; c < C_; c += 128) {
      float v = expf(row[c] - mx) * inv;
      g_p[(size_t)b * C_ + c] = v;
      sq += v * v;
    }
    red[t] = sq; __syncthreads();
    for (int s = 64; s > 0; s >>= 1) { if (t < s) red[t] += red[t + s]; __syncthreads(); }
    if (t == 0) g_rowsq[b] = red[0];
  } else if (blockIdx.x < 2 * B_) {
    int b = blockIdx.x - B_;
    float4 x = *(const float4*)(feat + (size_t)b * D_ + t * 4);
    float sq = x.x * x.x + x.y * x.y + x.z * x.z + x.w * x.w;
    red[t] = sq; __syncthreads();
    for (int s = 64; s > 0; s >>= 1) { if (t < s) red[t] += red[t + s]; __syncthreads(); }
    float inv = 1.f / fmaxf(sqrtf(red[0]), 1e-12f);
    x.x *= inv; x.y *= inv; x.z *= inv; x.w *= inv;
    *(float4*)(g_fn + (size_t)b * D_ + t * 4) = x;
    __nv_bfloat162 lo = __floats2bfloat162_rn(x.x, x.y);
    __nv_bfloat162 hi = __floats2bfloat162_rn(x.z, x.w);
    uint2 v; v.x = *(uint32_t*)&lo; v.y = *(uint32_t*)&hi;
    *(uint2*)(g_fnb + (size_t)b * D_ + t * 4) = v;
  } else {
    int i = (blockIdx.x - 2 * B_) * 128 + t;
    if (i < N_) g_owner[i] = -1;
  }
  __threadfence();
  __syncthreads();
  if (t == 0) {
    unsigned tk = atomicAdd(&g_tick1, 1u);
    isLast = ((tk % PREP_BLKS) == PREP_BLKS - 1) ? 1 : 0;
  }
  __syncthreads();
  if (isLast) {
    __threadfence();
    for (int j = t; j < B_; j += 128)
      atomicMax(&g_owner[clampN(trg[j])], j);
  }
}

/* --- bank fp32 -> bf16 with inline scatter + pad-zero; last block: colsum q --- */
__global__ void convert_k(const float* __restrict__ fb) {
  long idx = (long)blockIdx.x * 256 + threadIdx.x;
  long e = idx * 8;
  int row = (int)(e >> 9);
  int col = (int)(e & 511);
  if (row >= N_) {
    *(uint4*)(g_fbb + e) = make_uint4(0, 0, 0, 0);
  } else {
    int ow = g_owner[row];
    const float* src = (ow >= 0) ? (g_fn + (size_t)ow * D_) : (fb + (size_t)row * D_);
    float4 f0 = *(const float4*)(src + col);
    float4 f1 = *(const float4*)(src + col + 4);
    __nv_bfloat162 p0 = __floats2bfloat162_rn(f0.x, f0.y);
    __nv_bfloat162 p1 = __floats2bfloat162_rn(f0.z, f0.w);
    __nv_bfloat162 p2 = __floats2bfloat162_rn(f1.x, f1.y);
    __nv_bfloat162 p3 = __floats2bfloat162_rn(f1.z, f1.w);
    uint4 v;
    v.x = *(uint32_t*)&p0; v.y = *(uint32_t*)&p1;
    v.z = *(uint32_t*)&p2; v.w = *(uint32_t*)&p3;
    *(uint4*)(g_fbb + e) = v;
  }
  /* last block (pad rows, nearly idle): deterministic colsum q[c] = sum_b p[b][c] */
  if (blockIdx.x == CONV_BLKS - 1) {
    int t = threadIdx.x;
    for (int c = t; c < C_; c += 256) {
      float s0 = 0.f, s1 = 0.f, s2 = 0.f, s3 = 0.f,
            s4 = 0.f, s5 = 0.f, s6 = 0.f, s7 = 0.f;
      for (int bb = 0; bb < B_; bb += 8) {
        s0 += g_p[(size_t)(bb + 0) * C_ + c];
        s1 += g_p[(size_t)(bb + 1) * C_ + c];
        s2 += g_p[(size_t)(bb + 2) * C_ + c];
        s3 += g_p[(size_t)(bb + 3) * C_ + c];
        s4 += g_p[(size_t)(bb + 4) * C_ + c];
        s5 += g_p[(size_t)(bb + 5) * C_ + c];
        s6 += g_p[(size_t)(bb + 6) * C_ + c];
        s7 += g_p[(size_t)(bb + 7) * C_ + c];
      }
      g_q[c] = ((s0 + s1) + (s2 + s3)) + ((s4 + s5) + (s6 + s7));
    }
  }
}

/* ---- bf16 GEMM 128x64, warp tile 32x32, 4-stage cp.async, occ-3, fused top-6 ---- */
__global__ void __launch_bounds__(256, 3) gemm_k() {
  __shared__ __align__(16) char smemRaw[STAGES * STG_BYTES];   /* 61440 */

  const int tid  = threadIdx.x;
  const int lane = tid & 31;
  const int warp = tid >> 5;
  const int wm   = warp >> 1;
  const int wn   = warp & 1;
  const int mBase = blockIdx.x * BM;
  const int nBase = blockIdx.y * BN;

  const uint32_t smem0 = (uint32_t)__cvta_generic_to_shared(smemRaw);

  float acc[2][4][4];
#pragma unroll
  for (int i = 0; i < 2; i++)
#pragma unroll
    for (int j = 0; j < 4; j++)
#pragma unroll
      for (int k = 0; k < 4; k++) acc[i][j][k] = 0.f;

  uint32_t aAddr[2], bAddr[2];
  {
    int ar = wm * 32 + (lane & 15);
    int ac = (lane >> 4) * 16;
#pragma unroll
    for (int mi = 0; mi < 2; mi++) aAddr[mi] = smem0 + (ar + mi * 16) * 80 + ac;
    int bn = wn * 32 + (lane & 7) + ((lane >> 4) << 3);
    int bc = ((lane >> 3) & 1) * 16;
#pragma unroll
    for (int n2 = 0; n2 < 2; n2++) bAddr[n2] = smem0 + 10240 + (bn + n2 * 16) * 80 + bc;
  }

  const __nv_bfloat16* gA = g_fnb + (size_t)mBase * D_;
  const __nv_bfloat16* gB = g_fbb + (size_t)nBase * D_;

#define ISSUE_CHUNK(ch, stg) do {                                                   \
    uint32_t so = smem0 + (stg) * STG_BYTES;                                        \
    _Pragma("unroll")                                                               \
    for (int it = 0; it < 3; it++) {                                                \
      int idx = tid + it * 256;                                                     \
      if (idx < 512) {                                                              \
        int r = idx >> 2, c = idx & 3;                                              \
        CPASYNC16(so + r * 80 + c * 16, gA + (size_t)r * D_ + (ch) * BK + c * 8);   \
      } else {                                                                      \
        int j = idx - 512, r = j >> 2, c = j & 3;                                   \
        CPASYNC16(so + 10240 + r * 80 + c * 16,                                     \
                  gB + (size_t)r * D_ + (ch) * BK + c * 8);                         \
      }                                                                             \
    }                                                                               \
  } while (0)

  ISSUE_CHUNK(0, 0); CPCOMMIT();
  ISSUE_CHUNK(1, 1); CPCOMMIT();
  ISSUE_CHUNK(2, 2); CPCOMMIT();

#pragma unroll 1
  for (int ch = 0; ch < NCH; ch++) {
    const int stg = ch & (STAGES - 1);
    CPWAIT2();
    __syncthreads();
    if (ch + 3 < NCH) { ISSUE_CHUNK(ch + 3, (ch + 3) & (STAGES - 1)); CPCOMMIT(); }
    const uint32_t so = stg * STG_BYTES;
#pragma unroll
    for (int ks = 0; ks < 2; ks++) {
      uint32_t a[2][4], b2[2][4];
      const uint32_t koff = so + ks * 32;
#pragma unroll
      for (int mi = 0; mi < 2; mi++) LDSM4(a[mi], aAddr[mi] + koff);
#pragma unroll
      for (int n2 = 0; n2 < 2; n2++) LDSM4(b2[n2], bAddr[n2] + koff);
#pragma unroll
      for (int mi = 0; mi < 2; mi++)
#pragma unroll
        for (int ni = 0; ni < 4; ni++)
          MMA16816(acc[mi][ni], a[mi], b2[ni >> 1][(ni & 1) * 2], b2[ni >> 1][(ni & 1) * 2 + 1]);
    }
  }
  __syncthreads();

  /* ---- fused epilogue: per-row top-6 keys of this 64-col tile + tile-max key ---- */
  float* scanTile = (float*)smemRaw;            /* 128*65*4 = 33280 */
  u64*   mbK = (u64*)(smemRaw + 33280);         /* [128][2][6] = 12288 */

#pragma unroll
  for (int mi = 0; mi < 2; mi++) {
    int r = wm * 32 + mi * 16 + (lane >> 2);
#pragma unroll
    for (int ni = 0; ni < 4; ni++) {
      int c = wn * 32 + ni * 8 + (lane & 3) * 2;
      scanTile[r * 65 + c]           = acc[mi][ni][0];
      scanTile[r * 65 + c + 1]       = acc[mi][ni][1];
      scanTile[(r + 8) * 65 + c]     = acc[mi][ni][2];
      scanTile[(r + 8) * 65 + c + 1] = acc[mi][ni][3];
    }
  }
  __syncthreads();
  {
    int row = tid & 127;
    int seg = tid >> 7;
    int cs  = seg * 32;
    u64 s[6];
#pragma unroll
    for (int j = 0; j < 6; j++) s[j] = 0ull;
    if (nBase + BN <= N_) {
#pragma unroll 4
      for (int i = 0; i < 32; i++)
        ins6k(packkey(scanTile[row * 65 + cs + i], nBase + cs + i), s);
    } else {
#pragma unroll 4
      for (int i = 0; i < 32; i++) {
        int gcol = nBase + cs + i;
        if (gcol < N_) ins6k(packkey(scanTile[row * 65 + cs + i], gcol), s);
      }
    }
#pragma unroll
    for (int j = 0; j < 6; j++) mbK[(row * 2 + seg) * 6 + j] = s[j];
  }
  __syncthreads();
  if (tid < 128) {
    int row = tid;
    u64 s[6];
#pragma unroll
    for (int j = 0; j < 6; j++) s[j] = 0ull;
#pragma unroll
    for (int sg = 0; sg < 2; sg++)
#pragma unroll
      for (int j = 0; j < 6; j++)
        ins6k(mbK[(row * 2 + sg) * 6 + j], s);
    int grow = mBase + row;
    size_t base = ((size_t)grow * NT_N + blockIdx.y) * 6;
#pragma unroll
    for (int j = 0; j < 6; j++) g_cand[base + j] = s[j];
    g_tmaxk[(size_t)grow * NT_N + blockIdx.y] = s[0];
  }
}

/* ---- tail: top-6 tiles by tile-max key -> gather 36 keys -> top-6 ->
        warp-parallel KL; elected block: tiny final -> out[0] ---- */
__global__ void tail_k(const float* __restrict__ sb, float* __restrict__ out) {
  const int b = blockIdx.x, t = threadIdx.x;     /* 256 threads */
  const int lane = t & 31, warp = t >> 5;
  __shared__ u64  sv[256 * 6];                   /* 12288 */
  __shared__ u64  sv2[96];
  __shared__ int  stile[6];
  __shared__ u64  cK[36];
  __shared__ int  sidx[KN];
  __shared__ float redw[8];
  __shared__ int  isLast;

  /* phase 1: top-6 tile keys (782 keys, ~3 per thread, guarded branchless) */
  {
    const u64* tm = g_tmaxk + (size_t)b * NT_N;
    u64 s[6];
#pragma unroll
    for (int j = 0; j < 6; j++) s[j] = 0ull;
    for (int e = t; e < NT_N; e += 256) {
      /* re-pack key so idx = tile id (tile-max keys carry column idx) */
      ins6k((tm[e] & 0xFFFFFFFF00000000ull) | (unsigned)(0xFFFFFFFFu - e), s);
    }
#pragma unroll
    for (int j = 0; j < 6; j++) sv[t * 6 + j] = s[j];
  }
  __syncthreads();
  if (t < 16) {
    u64 s[6];
#pragma unroll
    for (int j = 0; j < 6; j++) s[j] = 0ull;
    for (int src = t * 16; src < t * 16 + 16; src++)
#pragma unroll
      for (int j = 0; j < 6; j++)
        ins6k(sv[src * 6 + j], s);
#pragma unroll
    for (int j = 0; j < 6; j++) sv2[t * 6 + j] = s[j];
  }
  __syncthreads();
  if (t == 0) {
    u64 s[6];
#pragma unroll
    for (int j = 0; j < 6; j++) s[j] = 0ull;
    for (int e = 0; e < 96; e++) ins6k(sv2[e], s);
#pragma unroll
    for (int j = 0; j < 6; j++) stile[j] = keyidx(s[j]);
  }
  __syncthreads();

  /* phase 2: gather the 6 chosen tiles' candidate key lists (36 keys) */
  if (t < 36) {
    int tile = stile[t / 6];
    cK[t] = g_cand[((size_t)b * NT_N + tile) * 6 + (t % 6)];
  }
  __syncthreads();
  if (t == 0) {
    u64 s[6];
#pragma unroll
    for (int j = 0; j < 6; j++) s[j] = 0ull;
    for (int e = 0; e < 36; e++) ins6k(cK[e], s);
#pragma unroll
    for (int j = 1; j < 6; j++) sidx[j - 1] = keyidx(s[j]);   /* drop rank-0 */
  }
  __syncthreads();

  /* warp-parallel KL: warp k (k<5) owns neighbor k */
  if (warp < KN) {
    int n  = sidx[warp];
    int ow = g_owner[n];
    const float* srow = (ow >= 0) ? (g_p + (size_t)ow * C_)
                                  : (sb + (size_t)n * C_);
    float ws = 0.f;
    for (int c = lane; c < C_; c += 32) {
      float s = srow[c];
      ws += s * (logf(s) - g_p[(size_t)b * C_ + c]);
    }
#pragma unroll
    for (int o = 16; o > 0; o >>= 1) ws += __shfl_xor_sync(0xffffffffu, ws, o);
    if (lane == 0) redw[warp] = ws;
  }
  __syncthreads();
  if (t == 0)
    g_lossparts[b] = ((redw[0] + redw[1]) + (redw[2] + redw[3])) + redw[4];

  /* election: last block does the tiny final reduction */
  __threadfence();
  __syncthreads();
  if (t == 0) {
    unsigned tk = atomicAdd(&g_tick2, 1u);
    isLast = ((tk % B_) == B_ - 1) ? 1 : 0;
  }
  __syncthreads();
  if (isLast) {
    __threadfence();
    __shared__ float r1[256], r2[256], r3[256];
    float q2 = 0.f;
    for (int c = t; c < C_; c += 256) { float q = g_q[c]; q2 += q * q; }
    r1[t] = g_lossparts[t];
    r2[t] = q2;
    r3[t] = g_rowsq[t];
    __syncthreads();
    for (int s = 128; s > 0; s >>= 1) {
      if (t < s) { r1[t] += r1[t + s]; r2[t] += r2[t + s]; r3[t] += r3[t + s]; }
      __syncthreads();
    }
    if (t == 0) out[0] = r1[0] / (float)B_ + 1.0f * ((r2[0] - r3[0]) / (float)B_);
  }
}

/* ---------------- launch: 4 kernels total ---------------- */
extern "C" void kernel_launch(void* const* d_in, const int* in_sizes, int n_in,
                              void* d_out, int out_size) {
  (void)in_sizes; (void)n_in; (void)out_size;
  const float* feat = (const float*)d_in[0];
  const float* pred = (const float*)d_in[1];
  const float* fb   = (const float*)d_in[2];
  const float* sb   = (const float*)d_in[3];
  const int*   trg  = (const int*)d_in[4];

  prep_k<<<PREP_BLKS, 128>>>(pred, feat, trg);
  convert_k<<<CONV_BLKS, 256>>>(fb);
  dim3 g(2, NT_N);
  gemm_k<<<g, 256>>>();
  tail_k<<<B_, 256>>>(sb, (float*)d_out);
}